// round 13
// baseline (speedup 1.0000x reference)
#include <cuda_runtime.h>

#define T_LEN   16777216
#define FULLMASK 0xffffffffu

// ---------------- halo kernel config ----------------
#define H_BLOCK  320
#define H_TILE   8192
#define H_HALO   2048
#define H_SPAN   (H_TILE + H_HALO)       // 10240
#define H_NT     (T_LEN / H_TILE)        // 2048
#define H_NWARP  (H_BLOCK / 32)          // 10
#define H_QSPAN  (H_SPAN / 4)            // 2560 quads

// ---------------- fallback (lookback) config ----------------
#define F_BLOCK  256
#define F_ITEMS  32
#define F_TILE   8192
#define F_NT     (T_LEN / F_TILE)        // 2048 = 1<<11
#define F_NTLOG2 11
#define F_NWARP  (F_BLOCK / 32)

__device__ unsigned g_ctr;
__device__ unsigned g_flag[F_NT];
__device__ float2   g_part[F_NT];
__device__ float2   g_incl[F_NT];

__device__ __forceinline__ unsigned ld_acquire(const unsigned* p) {
    unsigned v;
    asm volatile("ld.acquire.gpu.global.b32 %0, [%1];" : "=r"(v) : "l"(p) : "memory");
    return v;
}
__device__ __forceinline__ void st_release(unsigned* p, unsigned v) {
    asm volatile("st.release.gpu.global.b32 [%0], %1;" :: "l"(p), "r"(v) : "memory");
}
__device__ __forceinline__ float pow2k(float a, int k) {   // a^(2^k)
    #pragma unroll 1
    for (int i = 0; i < k; i++) a *= a;
    return a;
}

// ============================================================================
// Kernel A: independent halo tiles. Active iff a^2048 < 1e-10 (alpha >~ 0.0113).
// Each block scans SPAN=10240 elems from zero at the halo start; the carry-in
// discrepancy reaches outputs multiplied by <= a^2048 < 1e-10 (abs) -> far
// below the 1e-3 rel threshold. No flags, no atomics, no inter-block waits.
// Tile 0: zero-filled halo + closed-form pin  s_t += a^(t+1) * y0.
// ============================================================================
__global__ __launch_bounds__(H_BLOCK) void ses_halo(
    const float* __restrict__ y, const float* __restrict__ alpha_p,
    float* __restrict__ out)
{
    const float alpha = __ldg(alpha_p);
    const float a = 1.0f - alpha;
    if (!(pow2k(a, 11) < 1e-10f)) return;        // a^2048: not our regime

    // Padded transpose buffer: float4 slot = Q + (Q>>3). Conflict-free for
    // striped (consecutive Q) and blocked (Q = 8*tid + i) access.
    __shared__ float sbuf[H_SPAN + H_SPAN / 8];  // 11520 floats = 46 KB
    __shared__ float sh_wB[H_NWARP];

    const int tid  = threadIdx.x;
    const int lane = tid & 31;
    const int wid  = tid >> 5;
    const int tile = blockIdx.x;

    float4* s4 = reinterpret_cast<float4*>(sbuf);

    // ---- striped coalesced load of SPAN ending at tile end ----
    {
        const float4* y4 = reinterpret_cast<const float4*>(y);
        const int baseQ = tile * (H_TILE / 4) - (H_HALO / 4);  // -512 for tile 0
        #pragma unroll
        for (int j = 0; j < 8; j++) {
            const int Q = j * H_BLOCK + tid;
            const int gq = baseQ + Q;
            float4 val = (gq >= 0) ? y4[gq] : make_float4(0.f, 0.f, 0.f, 0.f);
            s4[Q + (Q >> 3)] = val;
        }
    }
    __syncthreads();

    // ---- blocked read (8 quads = 32 elems per thread) + serial scan ----
    float v[32];
    #pragma unroll
    for (int i = 0; i < 8; i++) {
        const int Q = 8 * tid + i;
        float4 q = s4[Q + (Q >> 3)];
        v[4*i+0] = q.x; v[4*i+1] = q.y; v[4*i+2] = q.z; v[4*i+3] = q.w;
    }
    float B;
    {
        float p = 0.f;
        #pragma unroll
        for (int i = 0; i < 32; i++) {
            p = fmaf(a, p, alpha * v[i]);
            v[i] = p;                            // local partial, zero carry-in
        }
        B = p;
    }

    float a2 = a*a, a4 = a2*a2, a8 = a4*a4, a16 = a8*a8;
    const float a32 = a16 * a16;

    // ---- warp inclusive scan of B; window-A closed form a^(32d) ----
    float m = a32;
    #pragma unroll
    for (int d = 1; d < 32; d <<= 1) {
        float pB = __shfl_up_sync(FULLMASK, B, d);
        if (lane >= d) B = fmaf(m, pB, B);
        m = m * m;
    }
    const float A1024 = m;                       // a^1024 per-warp A
    float exB = __shfl_up_sync(FULLMASK, B, 1);
    if (lane == 0) exB = 0.f;
    if (lane == 31) sh_wB[wid] = B;
    __syncthreads();

    float WB = 0.f;                              // prefix of warps 0..wid-1
    #pragma unroll
    for (int w = 0; w < H_NWARP; w++) if (w < wid) WB = fmaf(A1024, WB, sh_wB[w]);

    float exA = 1.f;                             // a^(32*lane)
    { float bp = a32; int e = lane;
      #pragma unroll
      for (int k = 0; k < 5; k++) { if (e & 1) exA *= bp; bp *= bp; e >>= 1; } }
    const float c = fmaf(exA, WB, exB);          // level just before this thread

    // ---- fixup ----
    {
        float cp = c * a;
        #pragma unroll
        for (int i = 0; i < 32; i++) { v[i] += cp; cp *= a; }
    }

    // ---- tile-0 pin correction: s_t += a^(t+1) * y0  (threads with g >= 0) ----
    if (tile == 0 && tid >= H_HALO / 32) {       // tid >= 64
        const float y0 = __ldg(y);
        float pw = a;                            // a^(32*(tid-64)) * a
        { float bp = a32; int e = tid - H_HALO / 32;
          #pragma unroll
          for (int k = 0; k < 8; k++) { if (e & 1) pw *= bp; bp *= bp; e >>= 1; } }
        #pragma unroll
        for (int i = 0; i < 32; i++) { v[i] = fmaf(pw, y0, v[i]); pw *= a; }
    }

    // ---- blocked -> SMEM (own slots), striped streaming stores ----
    #pragma unroll
    for (int i = 0; i < 8; i++) {
        const int Q = 8 * tid + i;
        s4[Q + (Q >> 3)] = make_float4(v[4*i+0], v[4*i+1], v[4*i+2], v[4*i+3]);
    }
    __syncthreads();

    {
        // output = local quads [512, 2560) -> global quad tile*2048 + (Q-512)
        float4* o4 = reinterpret_cast<float4*>(out) + (size_t)tile * (H_TILE / 4) - (H_HALO / 4);
        if (tile != H_NT - 1) {
            #pragma unroll
            for (int j = 0; j < 7; j++) {        // 7*320 = 2240 >= 2048
                const int Q = (H_HALO / 4) + j * H_BLOCK + tid;
                if (Q < H_QSPAN) __stcs(&o4[Q], s4[Q + (Q >> 3)]);
            }
        } else {
            const long long obase = (long long)tile * H_TILE - H_HALO;
            #pragma unroll
            for (int j = 0; j < 7; j++) {
                const int Q = (H_HALO / 4) + j * H_BLOCK + tid;
                if (Q >= H_QSPAN) continue;
                float4 q = s4[Q + (Q >> 3)];
                const long long g = obase + 4LL * Q;
                if (g + 4 <= (long long)(T_LEN - 1)) {
                    __stcs(&o4[Q], q);
                } else {
                    float* op = out + g;
                    if (g + 0 < (long long)(T_LEN - 1)) op[0] = q.x;
                    if (g + 1 < (long long)(T_LEN - 1)) op[1] = q.y;
                    if (g + 2 < (long long)(T_LEN - 1)) op[2] = q.z;
                    if (g + 3 < (long long)(T_LEN - 1)) op[3] = q.w;
                }
            }
        }
    }
}

// ============================================================================
// Kernel B: decoupled lookback with single-predecessor fast path.
// Active iff a^2048 >= 1e-10 (tiny alpha).
// ============================================================================
__global__ __launch_bounds__(F_BLOCK) void ses_scan_fb(
    const float* __restrict__ y, const float* __restrict__ alpha_p,
    float* __restrict__ out)
{
    const float alpha = __ldg(alpha_p);
    const float a = 1.0f - alpha;
    if (pow2k(a, 11) < 1e-10f) return;           // halo kernel handled it

    __shared__ float sbuf[F_TILE + F_TILE / 8];
    __shared__ float sh_wB[F_NWARP];
    __shared__ float sh_carry;
    __shared__ unsigned sh_ticket;

    const int tid  = threadIdx.x;
    const int lane = tid & 31;
    const int wid  = tid >> 5;

    if (tid == 0) sh_ticket = atomicAdd(&g_ctr, 1u);
    __syncthreads();
    const unsigned ticket = sh_ticket;
    const int tile = (int)(ticket & (F_NT - 1u));
    const unsigned fPart = 3u * (ticket >> F_NTLOG2) + 1u;
    const unsigned fIncl = fPart + 1u;

    float4* s4 = reinterpret_cast<float4*>(sbuf);
    {
        const float4* yin = reinterpret_cast<const float4*>(y) + (size_t)tile * (F_TILE / 4);
        #pragma unroll
        for (int j = 0; j < 8; j++) {
            const int Q = j * F_BLOCK + tid;
            s4[Q + (Q >> 3)] = yin[Q];
        }
    }
    __syncthreads();

    float v[F_ITEMS];
    #pragma unroll
    for (int i = 0; i < 8; i++) {
        const int Q = 8 * tid + i;
        float4 q = s4[Q + (Q >> 3)];
        v[4*i+0] = q.x; v[4*i+1] = q.y; v[4*i+2] = q.z; v[4*i+3] = q.w;
    }
    float B;
    {
        float p = 0.f;
        const bool first = (tile == 0 && tid == 0);
        #pragma unroll
        for (int i = 0; i < F_ITEMS; i++) {
            float aa = a, bb = alpha * v[i];
            if (first && i == 0) { aa = 0.f; bb = v[0]; }
            p = fmaf(aa, p, bb);
            v[i] = p;
        }
        B = p;
    }

    float a2 = a*a, a4 = a2*a2, a8 = a4*a4, a16 = a8*a8;
    const float a32 = a16 * a16;

    float m = a32;
    #pragma unroll
    for (int d = 1; d < 32; d <<= 1) {
        float pB = __shfl_up_sync(FULLMASK, B, d);
        if (lane >= d) B = fmaf(m, pB, B);
        m = m * m;
    }
    const float A1024 = m;
    float exB = __shfl_up_sync(FULLMASK, B, 1);
    if (lane == 0) exB = 0.f;
    if (lane == 31) sh_wB[wid] = B;
    __syncthreads();

    float WB = 0.f;
    #pragma unroll
    for (int w = 0; w < F_NWARP; w++) if (w < wid) WB = fmaf(A1024, WB, sh_wB[w]);

    float exA = 1.f;
    { float bp = a32; int e = lane;
      #pragma unroll
      for (int k = 0; k < 5; k++) { if (e & 1) exA *= bp; bp *= bp; e >>= 1; } }
    const float TexB = fmaf(exA, WB, exB);
    float TexA = exA;
    { float wp = A1024; int e = wid;
      #pragma unroll
      for (int k = 0; k < 3; k++) { if (e & 1) TexA *= wp; wp *= wp; e >>= 1; } }

    float aggA = 0.f, aggB = 0.f;
    if (tid == 0) {
        float gB = 0.f;
        #pragma unroll
        for (int w = 0; w < F_NWARP; w++) gB = fmaf(A1024, gB, sh_wB[w]);
        float A8192 = A1024 * A1024; A8192 *= A8192; A8192 *= A8192;
        aggA = (tile == 0) ? 0.f : A8192;
        aggB = gB;
        if (tile == 0) {
            __stcg(&g_incl[0], make_float2(0.f, gB));
            st_release(&g_flag[0], fIncl);
            sh_carry = 0.f;
        } else {
            __stcg(&g_part[tile], make_float2(A8192, gB));
            st_release(&g_flag[tile], fPart);
        }
    }

    if (wid == 0 && tile > 0) {
        __syncwarp();
        float accA, accB;
        bool done;
        int pred = tile - 1;
        {   // ---- fast path: wait only on the IMMEDIATE predecessor ----
            unsigned f = ld_acquire(&g_flag[pred]);
            while (f < fPart) { __nanosleep(32); f = ld_acquire(&g_flag[pred]); }
            float2 d2 = (f >= fIncl) ? __ldcg(&g_incl[pred]) : __ldcg(&g_part[pred]);
            accA = d2.x; accB = d2.y;
            done = (f >= fIncl) || (accA == 0.0f);
            pred--;
        }
        while (!done) {
            const int idx = pred - lane;
            unsigned st = 2u;
            if (idx >= 0) {
                unsigned f = ld_acquire(&g_flag[idx]);
                while (f < fPart) { __nanosleep(32); f = ld_acquire(&g_flag[idx]); }
                st = f - fPart + 1u;
            }
            float mA, mB;
            if (idx < 0) { mA = 1.f; mB = 0.f; }
            else {
                float2 d2 = (st == 2u) ? __ldcg(&g_incl[idx]) : __ldcg(&g_part[idx]);
                mA = d2.x; mB = d2.y;
            }
            const unsigned bal = __ballot_sync(FULLMASK, st == 2u);
            const int mm = bal ? (__ffs(bal) - 1) : 32;
            const int start = (mm < 32) ? mm : 31;

            float cA = 1.f, cB = 0.f;            // window earliest->latest
            for (int L = start; L >= 0; --L) {
                float sA = __shfl_sync(FULLMASK, mA, L);
                float sB = __shfl_sync(FULLMASK, mB, L);
                cB = fmaf(sA, cB, sB);
                cA = cA * sA;
            }
            float nB = fmaf(accA, cB, accB);     // acc = combine(window, acc)
            accA = cA * accA;
            accB = nB;
            done = (mm < 32) || (accA == 0.0f);
            pred -= 32;
        }
        if (lane == 0) {
            __stcg(&g_incl[tile], make_float2(accA * aggA, fmaf(aggA, accB, aggB)));
            st_release(&g_flag[tile], fIncl);
            sh_carry = accB;
        }
    }
    __syncthreads();

    const float c = fmaf(TexA, sh_carry, TexB);
    {
        float cp = c * a;
        #pragma unroll
        for (int i = 0; i < F_ITEMS; i++) { v[i] += cp; cp *= a; }
    }

    #pragma unroll
    for (int i = 0; i < 8; i++) {
        const int Q = 8 * tid + i;
        s4[Q + (Q >> 3)] = make_float4(v[4*i+0], v[4*i+1], v[4*i+2], v[4*i+3]);
    }
    __syncthreads();

    {
        float4* o4 = reinterpret_cast<float4*>(out) + (size_t)tile * (F_TILE / 4);
        if (tile != F_NT - 1) {
            #pragma unroll
            for (int j = 0; j < 8; j++) {
                const int Q = j * F_BLOCK + tid;
                __stcs(&o4[Q], s4[Q + (Q >> 3)]);
            }
        } else {
            const long long tbase = (long long)tile * F_TILE;
            #pragma unroll
            for (int j = 0; j < 8; j++) {
                const int Q = j * F_BLOCK + tid;
                float4 q = s4[Q + (Q >> 3)];
                const long long g = tbase + 4LL * Q;
                if (g + 4 <= (long long)(T_LEN - 1)) {
                    __stcs(&o4[Q], q);
                } else {
                    float* op = out + g;
                    if (g + 0 < (long long)(T_LEN - 1)) op[0] = q.x;
                    if (g + 1 < (long long)(T_LEN - 1)) op[1] = q.y;
                    if (g + 2 < (long long)(T_LEN - 1)) op[2] = q.z;
                    if (g + 3 < (long long)(T_LEN - 1)) op[3] = q.w;
                }
            }
        }
    }
}

extern "C" void kernel_launch(void* const* d_in, const int* in_sizes, int n_in,
                              void* d_out, int out_size) {
    const float* y     = (const float*)d_in[0];   // timeseries, T_LEN fp32
    const float* alpha = (const float*)d_in[1];   // 1 fp32
    float* out = (float*)d_out;                   // T_LEN-1 fp32
    (void)in_sizes; (void)n_in; (void)out_size;

    ses_halo<<<H_NT, H_BLOCK>>>(y, alpha, out);     // active iff a^2048 < 1e-10
    ses_scan_fb<<<F_NT, F_BLOCK>>>(y, alpha, out);  // active otherwise
}

// round 14
// speedup vs baseline: 1.7894x; 1.7894x over previous
#include <cuda_runtime.h>

#define T_LEN   16777216
#define FULLMASK 0xffffffffu

// ---------------- halo kernel config ----------------
#define H_BLOCK  320
#define H_TILE   8192
#define H_HALO   2048
#define H_SPAN   (H_TILE + H_HALO)       // 10240
#define H_NT     (T_LEN / H_TILE)        // 2048
#define H_NWARP  (H_BLOCK / 32)          // 10
#define H_QSPAN  (H_SPAN / 4)            // 2560 quads

// ---------------- fallback (lookback) config ----------------
#define F_BLOCK  256
#define F_ITEMS  32
#define F_TILE   8192
#define F_NT     (T_LEN / F_TILE)        // 2048 = 1<<11
#define F_NTLOG2 11
#define F_NWARP  (F_BLOCK / 32)

__device__ unsigned g_ctr;
__device__ unsigned g_flag[F_NT];
__device__ float2   g_part[F_NT];
__device__ float2   g_incl[F_NT];

__device__ __forceinline__ unsigned ld_acquire(const unsigned* p) {
    unsigned v;
    asm volatile("ld.acquire.gpu.global.b32 %0, [%1];" : "=r"(v) : "l"(p) : "memory");
    return v;
}
__device__ __forceinline__ void st_release(unsigned* p, unsigned v) {
    asm volatile("st.release.gpu.global.b32 [%0], %1;" :: "l"(p), "r"(v) : "memory");
}
__device__ __forceinline__ float pow2k(float a, int k) {   // a^(2^k)
    #pragma unroll 1
    for (int i = 0; i < k; i++) a *= a;
    return a;
}

// Activation gate for the halo path: a^2048 < 1e-5  (i.e. alpha > ~0.0056).
// Halo truncation error factor is then < 1e-5 absolute on O(sigma_level)
// values -> per-element rel err < ~4e-5, norm rel err far below the 1e-3
// threshold. For the observed alpha (~0.011), a^2048 ~ 1.7e-10: negligible.
__device__ __forceinline__ bool halo_active(float a) {
    return pow2k(a, 11) < 1e-5f;
}

// ============================================================================
// Kernel A: independent halo tiles (no flags / atomics / inter-block waits).
// Each block scans SPAN=10240 elems from zero at the halo start; the carry-in
// discrepancy reaches the stored outputs multiplied by <= a^2048.
// Tile 0: zero-filled halo + closed-form pin  s_t += a^(t+1) * y0.
// ============================================================================
__global__ __launch_bounds__(H_BLOCK) void ses_halo(
    const float* __restrict__ y, const float* __restrict__ alpha_p,
    float* __restrict__ out)
{
    const float alpha = __ldg(alpha_p);
    const float a = 1.0f - alpha;
    if (!halo_active(a)) return;                 // not our regime

    // Padded transpose buffer: float4 slot = Q + (Q>>3). Conflict-free for
    // striped (consecutive Q) and blocked (Q = 8*tid + i) access.
    __shared__ float sbuf[H_SPAN + H_SPAN / 8];  // 11520 floats = 46 KB
    __shared__ float sh_wB[H_NWARP];

    const int tid  = threadIdx.x;
    const int lane = tid & 31;
    const int wid  = tid >> 5;
    const int tile = blockIdx.x;

    float4* s4 = reinterpret_cast<float4*>(sbuf);

    // ---- striped coalesced load of SPAN ending at tile end ----
    {
        const float4* y4 = reinterpret_cast<const float4*>(y);
        const int baseQ = tile * (H_TILE / 4) - (H_HALO / 4);  // -512 for tile 0
        #pragma unroll
        for (int j = 0; j < 8; j++) {
            const int Q = j * H_BLOCK + tid;
            const int gq = baseQ + Q;
            float4 val = (gq >= 0) ? y4[gq] : make_float4(0.f, 0.f, 0.f, 0.f);
            s4[Q + (Q >> 3)] = val;
        }
    }
    __syncthreads();

    // ---- blocked read (8 quads = 32 elems per thread) + serial scan ----
    float v[32];
    #pragma unroll
    for (int i = 0; i < 8; i++) {
        const int Q = 8 * tid + i;
        float4 q = s4[Q + (Q >> 3)];
        v[4*i+0] = q.x; v[4*i+1] = q.y; v[4*i+2] = q.z; v[4*i+3] = q.w;
    }
    float B;
    {
        float p = 0.f;
        #pragma unroll
        for (int i = 0; i < 32; i++) {
            p = fmaf(a, p, alpha * v[i]);
            v[i] = p;                            // local partial, zero carry-in
        }
        B = p;
    }

    float a2 = a*a, a4 = a2*a2, a8 = a4*a4, a16 = a8*a8;
    const float a32 = a16 * a16;

    // ---- warp inclusive scan of B; window-A closed form a^(32d) ----
    float m = a32;
    #pragma unroll
    for (int d = 1; d < 32; d <<= 1) {
        float pB = __shfl_up_sync(FULLMASK, B, d);
        if (lane >= d) B = fmaf(m, pB, B);
        m = m * m;
    }
    const float A1024 = m;                       // a^1024 per-warp A
    float exB = __shfl_up_sync(FULLMASK, B, 1);
    if (lane == 0) exB = 0.f;
    if (lane == 31) sh_wB[wid] = B;
    __syncthreads();

    float WB = 0.f;                              // prefix of warps 0..wid-1
    #pragma unroll
    for (int w = 0; w < H_NWARP; w++) if (w < wid) WB = fmaf(A1024, WB, sh_wB[w]);

    float exA = 1.f;                             // a^(32*lane)
    { float bp = a32; int e = lane;
      #pragma unroll
      for (int k = 0; k < 5; k++) { if (e & 1) exA *= bp; bp *= bp; e >>= 1; } }
    const float c = fmaf(exA, WB, exB);          // level just before this thread

    // ---- fixup ----
    {
        float cp = c * a;
        #pragma unroll
        for (int i = 0; i < 32; i++) { v[i] += cp; cp *= a; }
    }

    // ---- tile-0 pin correction: s_t += a^(t+1) * y0  (threads with g >= 0) ----
    if (tile == 0 && tid >= H_HALO / 32) {       // tid >= 64
        const float y0 = __ldg(y);
        float pw = a;                            // a^(32*(tid-64)) * a
        { float bp = a32; int e = tid - H_HALO / 32;
          #pragma unroll
          for (int k = 0; k < 8; k++) { if (e & 1) pw *= bp; bp *= bp; e >>= 1; } }
        #pragma unroll
        for (int i = 0; i < 32; i++) { v[i] = fmaf(pw, y0, v[i]); pw *= a; }
    }

    // ---- blocked -> SMEM (own slots), striped streaming stores ----
    #pragma unroll
    for (int i = 0; i < 8; i++) {
        const int Q = 8 * tid + i;
        s4[Q + (Q >> 3)] = make_float4(v[4*i+0], v[4*i+1], v[4*i+2], v[4*i+3]);
    }
    __syncthreads();

    {
        // output = local quads [512, 2560) -> global quad tile*2048 + (Q-512)
        float4* o4 = reinterpret_cast<float4*>(out) + (size_t)tile * (H_TILE / 4) - (H_HALO / 4);
        if (tile != H_NT - 1) {
            #pragma unroll
            for (int j = 0; j < 7; j++) {        // 7*320 = 2240 >= 2048
                const int Q = (H_HALO / 4) + j * H_BLOCK + tid;
                if (Q < H_QSPAN) __stcs(&o4[Q], s4[Q + (Q >> 3)]);
            }
        } else {
            const long long obase = (long long)tile * H_TILE - H_HALO;
            #pragma unroll
            for (int j = 0; j < 7; j++) {
                const int Q = (H_HALO / 4) + j * H_BLOCK + tid;
                if (Q >= H_QSPAN) continue;
                float4 q = s4[Q + (Q >> 3)];
                const long long g = obase + 4LL * Q;
                if (g + 4 <= (long long)(T_LEN - 1)) {
                    __stcs(&o4[Q], q);
                } else {
                    float* op = out + g;
                    if (g + 0 < (long long)(T_LEN - 1)) op[0] = q.x;
                    if (g + 1 < (long long)(T_LEN - 1)) op[1] = q.y;
                    if (g + 2 < (long long)(T_LEN - 1)) op[2] = q.z;
                    if (g + 3 < (long long)(T_LEN - 1)) op[3] = q.w;
                }
            }
        }
    }
}

// ============================================================================
// Kernel B: decoupled lookback with single-predecessor fast path.
// Active iff the halo gate fails (tiny alpha).
// ============================================================================
__global__ __launch_bounds__(F_BLOCK) void ses_scan_fb(
    const float* __restrict__ y, const float* __restrict__ alpha_p,
    float* __restrict__ out)
{
    const float alpha = __ldg(alpha_p);
    const float a = 1.0f - alpha;
    if (halo_active(a)) return;                  // halo kernel handled it

    __shared__ float sbuf[F_TILE + F_TILE / 8];
    __shared__ float sh_wB[F_NWARP];
    __shared__ float sh_carry;
    __shared__ unsigned sh_ticket;

    const int tid  = threadIdx.x;
    const int lane = tid & 31;
    const int wid  = tid >> 5;

    if (tid == 0) sh_ticket = atomicAdd(&g_ctr, 1u);
    __syncthreads();
    const unsigned ticket = sh_ticket;
    const int tile = (int)(ticket & (F_NT - 1u));
    const unsigned fPart = 3u * (ticket >> F_NTLOG2) + 1u;
    const unsigned fIncl = fPart + 1u;

    float4* s4 = reinterpret_cast<float4*>(sbuf);
    {
        const float4* yin = reinterpret_cast<const float4*>(y) + (size_t)tile * (F_TILE / 4);
        #pragma unroll
        for (int j = 0; j < 8; j++) {
            const int Q = j * F_BLOCK + tid;
            s4[Q + (Q >> 3)] = yin[Q];
        }
    }
    __syncthreads();

    float v[F_ITEMS];
    #pragma unroll
    for (int i = 0; i < 8; i++) {
        const int Q = 8 * tid + i;
        float4 q = s4[Q + (Q >> 3)];
        v[4*i+0] = q.x; v[4*i+1] = q.y; v[4*i+2] = q.z; v[4*i+3] = q.w;
    }
    float B;
    {
        float p = 0.f;
        const bool first = (tile == 0 && tid == 0);
        #pragma unroll
        for (int i = 0; i < F_ITEMS; i++) {
            float aa = a, bb = alpha * v[i];
            if (first && i == 0) { aa = 0.f; bb = v[0]; }
            p = fmaf(aa, p, bb);
            v[i] = p;
        }
        B = p;
    }

    float a2 = a*a, a4 = a2*a2, a8 = a4*a4, a16 = a8*a8;
    const float a32 = a16 * a16;

    float m = a32;
    #pragma unroll
    for (int d = 1; d < 32; d <<= 1) {
        float pB = __shfl_up_sync(FULLMASK, B, d);
        if (lane >= d) B = fmaf(m, pB, B);
        m = m * m;
    }
    const float A1024 = m;
    float exB = __shfl_up_sync(FULLMASK, B, 1);
    if (lane == 0) exB = 0.f;
    if (lane == 31) sh_wB[wid] = B;
    __syncthreads();

    float WB = 0.f;
    #pragma unroll
    for (int w = 0; w < F_NWARP; w++) if (w < wid) WB = fmaf(A1024, WB, sh_wB[w]);

    float exA = 1.f;
    { float bp = a32; int e = lane;
      #pragma unroll
      for (int k = 0; k < 5; k++) { if (e & 1) exA *= bp; bp *= bp; e >>= 1; } }
    const float TexB = fmaf(exA, WB, exB);
    float TexA = exA;
    { float wp = A1024; int e = wid;
      #pragma unroll
      for (int k = 0; k < 3; k++) { if (e & 1) TexA *= wp; wp *= wp; e >>= 1; } }

    float aggA = 0.f, aggB = 0.f;
    if (tid == 0) {
        float gB = 0.f;
        #pragma unroll
        for (int w = 0; w < F_NWARP; w++) gB = fmaf(A1024, gB, sh_wB[w]);
        float A8192 = A1024 * A1024; A8192 *= A8192; A8192 *= A8192;
        aggA = (tile == 0) ? 0.f : A8192;
        aggB = gB;
        if (tile == 0) {
            __stcg(&g_incl[0], make_float2(0.f, gB));
            st_release(&g_flag[0], fIncl);
            sh_carry = 0.f;
        } else {
            __stcg(&g_part[tile], make_float2(A8192, gB));
            st_release(&g_flag[tile], fPart);
        }
    }

    if (wid == 0 && tile > 0) {
        __syncwarp();
        float accA, accB;
        bool done;
        int pred = tile - 1;
        {   // fast path: wait only on the IMMEDIATE predecessor
            unsigned f = ld_acquire(&g_flag[pred]);
            while (f < fPart) { __nanosleep(32); f = ld_acquire(&g_flag[pred]); }
            float2 d2 = (f >= fIncl) ? __ldcg(&g_incl[pred]) : __ldcg(&g_part[pred]);
            accA = d2.x; accB = d2.y;
            done = (f >= fIncl) || (accA == 0.0f);
            pred--;
        }
        while (!done) {
            const int idx = pred - lane;
            unsigned st = 2u;
            if (idx >= 0) {
                unsigned f = ld_acquire(&g_flag[idx]);
                while (f < fPart) { __nanosleep(32); f = ld_acquire(&g_flag[idx]); }
                st = f - fPart + 1u;
            }
            float mA, mB;
            if (idx < 0) { mA = 1.f; mB = 0.f; }
            else {
                float2 d2 = (st == 2u) ? __ldcg(&g_incl[idx]) : __ldcg(&g_part[idx]);
                mA = d2.x; mB = d2.y;
            }
            const unsigned bal = __ballot_sync(FULLMASK, st == 2u);
            const int mm = bal ? (__ffs(bal) - 1) : 32;
            const int start = (mm < 32) ? mm : 31;

            float cA = 1.f, cB = 0.f;            // window earliest->latest
            for (int L = start; L >= 0; --L) {
                float sA = __shfl_sync(FULLMASK, mA, L);
                float sB = __shfl_sync(FULLMASK, mB, L);
                cB = fmaf(sA, cB, sB);
                cA = cA * sA;
            }
            float nB = fmaf(accA, cB, accB);     // acc = combine(window, acc)
            accA = cA * accA;
            accB = nB;
            done = (mm < 32) || (accA == 0.0f);
            pred -= 32;
        }
        if (lane == 0) {
            __stcg(&g_incl[tile], make_float2(accA * aggA, fmaf(aggA, accB, aggB)));
            st_release(&g_flag[tile], fIncl);
            sh_carry = accB;
        }
    }
    __syncthreads();

    const float c = fmaf(TexA, sh_carry, TexB);
    {
        float cp = c * a;
        #pragma unroll
        for (int i = 0; i < F_ITEMS; i++) { v[i] += cp; cp *= a; }
    }

    #pragma unroll
    for (int i = 0; i < 8; i++) {
        const int Q = 8 * tid + i;
        s4[Q + (Q >> 3)] = make_float4(v[4*i+0], v[4*i+1], v[4*i+2], v[4*i+3]);
    }
    __syncthreads();

    {
        float4* o4 = reinterpret_cast<float4*>(out) + (size_t)tile * (F_TILE / 4);
        if (tile != F_NT - 1) {
            #pragma unroll
            for (int j = 0; j < 8; j++) {
                const int Q = j * F_BLOCK + tid;
                __stcs(&o4[Q], s4[Q + (Q >> 3)]);
            }
        } else {
            const long long tbase = (long long)tile * F_TILE;
            #pragma unroll
            for (int j = 0; j < 8; j++) {
                const int Q = j * F_BLOCK + tid;
                float4 q = s4[Q + (Q >> 3)];
                const long long g = tbase + 4LL * Q;
                if (g + 4 <= (long long)(T_LEN - 1)) {
                    __stcs(&o4[Q], q);
                } else {
                    float* op = out + g;
                    if (g + 0 < (long long)(T_LEN - 1)) op[0] = q.x;
                    if (g + 1 < (long long)(T_LEN - 1)) op[1] = q.y;
                    if (g + 2 < (long long)(T_LEN - 1)) op[2] = q.z;
                    if (g + 3 < (long long)(T_LEN - 1)) op[3] = q.w;
                }
            }
        }
    }
}

extern "C" void kernel_launch(void* const* d_in, const int* in_sizes, int n_in,
                              void* d_out, int out_size) {
    const float* y     = (const float*)d_in[0];   // timeseries, T_LEN fp32
    const float* alpha = (const float*)d_in[1];   // 1 fp32
    float* out = (float*)d_out;                   // T_LEN-1 fp32
    (void)in_sizes; (void)n_in; (void)out_size;

    ses_halo<<<H_NT, H_BLOCK>>>(y, alpha, out);     // active iff a^2048 < 1e-5
    ses_scan_fb<<<F_NT, F_BLOCK>>>(y, alpha, out);  // active otherwise
}

// round 15
// speedup vs baseline: 1.9925x; 1.1135x over previous
#include <cuda_runtime.h>

#define T_LEN   16777216
#define FULLMASK 0xffffffffu

#define BLOCKT   320                     // 10 warps
#define NT       2048                    // tiles (= grid)
#define NT_LOG2  11

// ---------------- halo path config ----------------
#define H_TILE   8192
#define H_HALO   2048
#define H_SPAN   (H_TILE + H_HALO)       // 10240
#define H_NWARP  10
#define H_QSPAN  (H_SPAN / 4)            // 2560 quads

// ---------------- fallback path config (works on tid < 256) ----------------
#define F_WORK   256
#define F_ITEMS  32
#define F_TILE   8192
#define F_NWARP  8

__device__ unsigned g_ctr;
__device__ unsigned g_flag[NT];
__device__ float2   g_part[NT];
__device__ float2   g_incl[NT];

__device__ __forceinline__ unsigned ld_acquire(const unsigned* p) {
    unsigned v;
    asm volatile("ld.acquire.gpu.global.b32 %0, [%1];" : "=r"(v) : "l"(p) : "memory");
    return v;
}
__device__ __forceinline__ void st_release(unsigned* p, unsigned v) {
    asm volatile("st.release.gpu.global.b32 [%0], %1;" :: "l"(p), "r"(v) : "memory");
}
__device__ __forceinline__ float pow2k(float a, int k) {   // a^(2^k)
    #pragma unroll 1
    for (int i = 0; i < k; i++) a *= a;
    return a;
}
// Halo path gate: a^2048 < 1e-5 (alpha > ~0.0056). Truncation error factor
// < 1e-5 absolute on O(sigma) values -> orders below the 1e-3 threshold.
__device__ __forceinline__ bool halo_active(float a) {
    return pow2k(a, 11) < 1e-5f;
}

__global__ __launch_bounds__(BLOCKT) void ses_fused(
    const float* __restrict__ y, const float* __restrict__ alpha_p,
    float* __restrict__ out)
{
    // Padded transpose buffer: float4 slot = Q + (Q>>3). Conflict-free for
    // striped (consecutive Q) and blocked (Q = 8*tid + i) access.
    __shared__ float sbuf[H_SPAN + H_SPAN / 8];     // 46 KB (covers both paths)
    __shared__ float sh_wB[H_NWARP];
    __shared__ float sh_carry;
    __shared__ unsigned sh_ticket;

    const int tid  = threadIdx.x;
    const int lane = tid & 31;
    const int wid  = tid >> 5;

    const float alpha = __ldg(alpha_p);
    const float a = 1.0f - alpha;

    float a2 = a*a, a4 = a2*a2, a8 = a4*a4, a16 = a8*a8;
    const float a32 = a16 * a16;
    float4* s4 = reinterpret_cast<float4*>(sbuf);

    if (halo_active(a)) {
        // ====================================================================
        // HALO PATH: fully independent tiles. Zero flags/atomics/waits.
        // Scan SPAN=10240 from zero at halo start; carry-in discrepancy is
        // attenuated by a^2048 < 1e-5 before reaching any stored output.
        // ====================================================================
        const int tile = blockIdx.x;

        // ---- striped coalesced load of SPAN ending at tile end ----
        {
            const float4* y4 = reinterpret_cast<const float4*>(y);
            const int baseQ = tile * (H_TILE / 4) - (H_HALO / 4);  // -512 @ tile 0
            #pragma unroll
            for (int j = 0; j < 8; j++) {
                const int Q = j * BLOCKT + tid;                    // covers 0..2559
                const int gq = baseQ + Q;
                float4 val = (gq >= 0) ? y4[gq] : make_float4(0.f, 0.f, 0.f, 0.f);
                s4[Q + (Q >> 3)] = val;
            }
        }
        __syncthreads();

        // ---- blocked read (32 elems/thread) + serial scan, zero carry-in ----
        float v[32];
        #pragma unroll
        for (int i = 0; i < 8; i++) {
            const int Q = 8 * tid + i;
            float4 q = s4[Q + (Q >> 3)];
            v[4*i+0] = q.x; v[4*i+1] = q.y; v[4*i+2] = q.z; v[4*i+3] = q.w;
        }
        float B;
        {
            float p = 0.f;
            #pragma unroll
            for (int i = 0; i < 32; i++) {
                p = fmaf(a, p, alpha * v[i]);
                v[i] = p;
            }
            B = p;
        }

        // ---- warp inclusive scan of B; window-A closed form a^(32d) ----
        float m = a32;
        #pragma unroll
        for (int d = 1; d < 32; d <<= 1) {
            float pB = __shfl_up_sync(FULLMASK, B, d);
            if (lane >= d) B = fmaf(m, pB, B);
            m = m * m;
        }
        const float A1024 = m;
        float exB = __shfl_up_sync(FULLMASK, B, 1);
        if (lane == 0) exB = 0.f;
        if (lane == 31) sh_wB[wid] = B;
        __syncthreads();

        float WB = 0.f;                          // prefix of warps 0..wid-1
        #pragma unroll
        for (int w = 0; w < H_NWARP; w++) if (w < wid) WB = fmaf(A1024, WB, sh_wB[w]);

        float exA = 1.f;                         // a^(32*lane)
        { float bp = a32; int e = lane;
          #pragma unroll
          for (int k = 0; k < 5; k++) { if (e & 1) exA *= bp; bp *= bp; e >>= 1; } }
        const float c = fmaf(exA, WB, exB);      // level just before this thread

        {
            float cp = c * a;
            #pragma unroll
            for (int i = 0; i < 32; i++) { v[i] += cp; cp *= a; }
        }

        // ---- tile-0 pin: s_t += a^(t+1) * y0  (threads with global idx >= 0) ----
        if (tile == 0 && tid >= H_HALO / 32) {   // tid >= 64
            const float y0 = __ldg(y);
            float pw = a;                        // a^(32*(tid-64)) * a
            { float bp = a32; int e = tid - H_HALO / 32;
              #pragma unroll
              for (int k = 0; k < 8; k++) { if (e & 1) pw *= bp; bp *= bp; e >>= 1; } }
            #pragma unroll
            for (int i = 0; i < 32; i++) { v[i] = fmaf(pw, y0, v[i]); pw *= a; }
        }

        // ---- blocked -> SMEM (own slots), striped streaming stores ----
        #pragma unroll
        for (int i = 0; i < 8; i++) {
            const int Q = 8 * tid + i;
            s4[Q + (Q >> 3)] = make_float4(v[4*i+0], v[4*i+1], v[4*i+2], v[4*i+3]);
        }
        __syncthreads();

        {
            // output = local quads [512, 2560) -> global quad tile*2048 + (Q-512)
            float4* o4 = reinterpret_cast<float4*>(out) + (size_t)tile * (H_TILE / 4) - (H_HALO / 4);
            if (tile != NT - 1) {
                #pragma unroll
                for (int j = 0; j < 7; j++) {    // 7*320 covers 2048 quads
                    const int Q = (H_HALO / 4) + j * BLOCKT + tid;
                    if (Q < H_QSPAN) __stcs(&o4[Q], s4[Q + (Q >> 3)]);
                }
            } else {
                const long long obase = (long long)tile * H_TILE - H_HALO;
                #pragma unroll
                for (int j = 0; j < 7; j++) {
                    const int Q = (H_HALO / 4) + j * BLOCKT + tid;
                    if (Q >= H_QSPAN) continue;
                    float4 q = s4[Q + (Q >> 3)];
                    const long long g = obase + 4LL * Q;
                    if (g + 4 <= (long long)(T_LEN - 1)) {
                        __stcs(&o4[Q], q);
                    } else {
                        float* op = out + g;
                        if (g + 0 < (long long)(T_LEN - 1)) op[0] = q.x;
                        if (g + 1 < (long long)(T_LEN - 1)) op[1] = q.y;
                        if (g + 2 < (long long)(T_LEN - 1)) op[2] = q.z;
                        if (g + 3 < (long long)(T_LEN - 1)) op[3] = q.w;
                    }
                }
            }
        }
        return;
    }

    // ========================================================================
    // FALLBACK PATH (tiny alpha): decoupled lookback with generation flags.
    // Work is done by tid < 256 (8 warps); warps 8-9 join barriers only.
    // ========================================================================
    if (tid == 0) sh_ticket = atomicAdd(&g_ctr, 1u);
    __syncthreads();
    const unsigned ticket = sh_ticket;
    const int tile = (int)(ticket & (NT - 1u));
    const unsigned fPart = 3u * (ticket >> NT_LOG2) + 1u;
    const unsigned fIncl = fPart + 1u;

    {
        const float4* yin = reinterpret_cast<const float4*>(y) + (size_t)tile * (F_TILE / 4);
        #pragma unroll
        for (int j = 0; j < 7; j++) {            // 7*320 >= 2048
            const int Q = j * BLOCKT + tid;
            if (Q < F_TILE / 4) s4[Q + (Q >> 3)] = yin[Q];
        }
    }
    __syncthreads();

    float v[F_ITEMS];
    float B = 0.f, TexA = 1.f, TexB = 0.f, A1024 = 0.f;
    if (tid < F_WORK) {
        #pragma unroll
        for (int i = 0; i < 8; i++) {
            const int Q = 8 * tid + i;
            float4 q = s4[Q + (Q >> 3)];
            v[4*i+0] = q.x; v[4*i+1] = q.y; v[4*i+2] = q.z; v[4*i+3] = q.w;
        }
        {
            float p = 0.f;
            const bool first = (tile == 0 && tid == 0);
            #pragma unroll
            for (int i = 0; i < F_ITEMS; i++) {
                float aa = a, bb = alpha * v[i];
                if (first && i == 0) { aa = 0.f; bb = v[0]; }
                p = fmaf(aa, p, bb);
                v[i] = p;
            }
            B = p;
        }

        float m = a32;
        #pragma unroll
        for (int d = 1; d < 32; d <<= 1) {
            float pB = __shfl_up_sync(FULLMASK, B, d);
            if (lane >= d) B = fmaf(m, pB, B);
            m = m * m;
        }
        A1024 = m;
        float exB = __shfl_up_sync(FULLMASK, B, 1);
        if (lane == 0) exB = 0.f;
        if (lane == 31) sh_wB[wid] = B;
    }
    __syncthreads();

    if (tid < F_WORK) {
        float WB = 0.f;
        #pragma unroll
        for (int w = 0; w < F_NWARP; w++) if (w < wid) WB = fmaf(A1024, WB, sh_wB[w]);
        float exA = 1.f;
        { float bp = a32; int e = lane;
          #pragma unroll
          for (int k = 0; k < 5; k++) { if (e & 1) exA *= bp; bp *= bp; e >>= 1; } }
        float exB = __shfl_up_sync(FULLMASK, B, 1);      // recompute lane-exclusive
        if (lane == 0) exB = 0.f;
        TexB = fmaf(exA, WB, exB);
        TexA = exA;
        { float wp = A1024; int e = wid;
          #pragma unroll
          for (int k = 0; k < 3; k++) { if (e & 1) TexA *= wp; wp *= wp; e >>= 1; } }
    }

    float aggA = 0.f, aggB = 0.f;
    if (tid == 0) {
        float gB = 0.f;
        #pragma unroll
        for (int w = 0; w < F_NWARP; w++) gB = fmaf(A1024, gB, sh_wB[w]);
        float A8192 = A1024 * A1024; A8192 *= A8192; A8192 *= A8192;
        aggA = (tile == 0) ? 0.f : A8192;
        aggB = gB;
        if (tile == 0) {
            __stcg(&g_incl[0], make_float2(0.f, gB));
            st_release(&g_flag[0], fIncl);
            sh_carry = 0.f;
        } else {
            __stcg(&g_part[tile], make_float2(A8192, gB));
            st_release(&g_flag[tile], fPart);
        }
    }

    if (wid == 0 && tile > 0) {
        __syncwarp();
        float accA, accB;
        bool done;
        int pred = tile - 1;
        {   // fast path: wait only on the IMMEDIATE predecessor
            unsigned f = ld_acquire(&g_flag[pred]);
            while (f < fPart) { __nanosleep(32); f = ld_acquire(&g_flag[pred]); }
            float2 d2 = (f >= fIncl) ? __ldcg(&g_incl[pred]) : __ldcg(&g_part[pred]);
            accA = d2.x; accB = d2.y;
            done = (f >= fIncl) || (accA == 0.0f);
            pred--;
        }
        while (!done) {
            const int idx = pred - lane;
            unsigned st = 2u;
            if (idx >= 0) {
                unsigned f = ld_acquire(&g_flag[idx]);
                while (f < fPart) { __nanosleep(32); f = ld_acquire(&g_flag[idx]); }
                st = f - fPart + 1u;
            }
            float mA, mB;
            if (idx < 0) { mA = 1.f; mB = 0.f; }
            else {
                float2 d2 = (st == 2u) ? __ldcg(&g_incl[idx]) : __ldcg(&g_part[idx]);
                mA = d2.x; mB = d2.y;
            }
            const unsigned bal = __ballot_sync(FULLMASK, st == 2u);
            const int mm = bal ? (__ffs(bal) - 1) : 32;
            const int start = (mm < 32) ? mm : 31;

            float cA = 1.f, cB = 0.f;            // window earliest->latest
            for (int L = start; L >= 0; --L) {
                float sA = __shfl_sync(FULLMASK, mA, L);
                float sB = __shfl_sync(FULLMASK, mB, L);
                cB = fmaf(sA, cB, sB);
                cA = cA * sA;
            }
            float nB = fmaf(accA, cB, accB);     // acc = combine(window, acc)
            accA = cA * accA;
            accB = nB;
            done = (mm < 32) || (accA == 0.0f);
            pred -= 32;
        }
        if (lane == 0) {
            __stcg(&g_incl[tile], make_float2(accA * aggA, fmaf(aggA, accB, aggB)));
            st_release(&g_flag[tile], fIncl);
            sh_carry = accB;
        }
    }
    __syncthreads();

    if (tid < F_WORK) {
        const float c = fmaf(TexA, sh_carry, TexB);
        float cp = c * a;
        #pragma unroll
        for (int i = 0; i < F_ITEMS; i++) { v[i] += cp; cp *= a; }

        #pragma unroll
        for (int i = 0; i < 8; i++) {
            const int Q = 8 * tid + i;
            s4[Q + (Q >> 3)] = make_float4(v[4*i+0], v[4*i+1], v[4*i+2], v[4*i+3]);
        }
    }
    __syncthreads();

    {
        float4* o4 = reinterpret_cast<float4*>(out) + (size_t)tile * (F_TILE / 4);
        if (tile != NT - 1) {
            #pragma unroll
            for (int j = 0; j < 7; j++) {
                const int Q = j * BLOCKT + tid;
                if (Q < F_TILE / 4) __stcs(&o4[Q], s4[Q + (Q >> 3)]);
            }
        } else {
            const long long tbase = (long long)tile * F_TILE;
            #pragma unroll
            for (int j = 0; j < 7; j++) {
                const int Q = j * BLOCKT + tid;
                if (Q >= F_TILE / 4) continue;
                float4 q = s4[Q + (Q >> 3)];
                const long long g = tbase + 4LL * Q;
                if (g + 4 <= (long long)(T_LEN - 1)) {
                    __stcs(&o4[Q], q);
                } else {
                    float* op = out + g;
                    if (g + 0 < (long long)(T_LEN - 1)) op[0] = q.x;
                    if (g + 1 < (long long)(T_LEN - 1)) op[1] = q.y;
                    if (g + 2 < (long long)(T_LEN - 1)) op[2] = q.z;
                    if (g + 3 < (long long)(T_LEN - 1)) op[3] = q.w;
                }
            }
        }
    }
}

extern "C" void kernel_launch(void* const* d_in, const int* in_sizes, int n_in,
                              void* d_out, int out_size) {
    const float* y     = (const float*)d_in[0];   // timeseries, T_LEN fp32
    const float* alpha = (const float*)d_in[1];   // 1 fp32
    float* out = (float*)d_out;                   // T_LEN-1 fp32
    (void)in_sizes; (void)n_in; (void)out_size;

    ses_fused<<<NT, BLOCKT>>>(y, alpha, out);     // one launch; internal dispatch
}

// round 16
// speedup vs baseline: 2.1792x; 1.0937x over previous
#include <cuda_runtime.h>

#define T_LEN   16777216
#define FULLMASK 0xffffffffu

#define BLOCKT   320                     // 10 warps
#define NT       2048                    // tiles = grid
#define NT_LOG2  11

// ---------------- halo path config ----------------
#define H_TILE   8192                    // output elems per tile (2048 quads)
#define H_HALOQ  512                     // halo quads (2048 elems)
#define H_NPH    8                       // phases: 8*320 = 2560 quads = 10240 elems
#define LASTQ    (T_LEN / 4 - 1)         // 4194303

// ---------------- fallback path config (works on tid < 256) ----------------
#define F_WORK   256
#define F_ITEMS  32
#define F_TILE   8192
#define F_NWARP  8
#define F_SMEM   ((F_TILE + F_TILE / 8) * 4)   // 36864 B padded buffer

__device__ unsigned g_ctr;
__device__ unsigned g_flag[NT];
__device__ float2   g_part[NT];
__device__ float2   g_incl[NT];

__device__ __forceinline__ unsigned ld_acquire(const unsigned* p) {
    unsigned v;
    asm volatile("ld.acquire.gpu.global.b32 %0, [%1];" : "=r"(v) : "l"(p) : "memory");
    return v;
}
__device__ __forceinline__ void st_release(unsigned* p, unsigned v) {
    asm volatile("st.release.gpu.global.b32 [%0], %1;" :: "l"(p), "r"(v) : "memory");
}
__device__ __forceinline__ float pow2k(float a, int k) {   // a^(2^k)
    #pragma unroll 1
    for (int i = 0; i < k; i++) a *= a;
    return a;
}
__device__ __forceinline__ float powi(float base, int e, int bits) {  // base^e
    float r = 1.f;
    #pragma unroll 1
    for (int k = 0; k < bits; k++) { if (e & 1) r *= base; base *= base; e >>= 1; }
    return r;
}
// Halo gate: a^2048 < 1e-5 (alpha > ~0.0056): truncation error factor < 1e-5
// absolute on O(sigma) values -> orders below the 1e-3 threshold.
__device__ __forceinline__ bool halo_active(float a) {
    return pow2k(a, 11) < 1e-5f;
}

__global__ __launch_bounds__(BLOCKT, 3) void ses_fused(
    const float* __restrict__ y, const float* __restrict__ alpha_p,
    float* __restrict__ out)
{
    extern __shared__ float sdyn[];            // fallback transpose buffer only
    __shared__ float sh_agg[80];               // region aggregates (halo path)
    __shared__ float sh_P[80];                 // region exclusive prefixes
    __shared__ float sh_wB[F_NWARP];           // fallback
    __shared__ float sh_carry;
    __shared__ unsigned sh_ticket;

    const int tid  = threadIdx.x;
    const int lane = tid & 31;
    const int wid  = tid >> 5;

    const float alpha = __ldg(alpha_p);
    const float a = 1.0f - alpha;
    const float a2 = a * a, a3 = a2 * a, a4 = a2 * a2;

    if (halo_active(a)) {
        // ====================================================================
        // HALO PATH — striped registers, NO data transpose, NO inter-block dep.
        // Region (j,w) = quads [320j+32w, +32) = contiguous 128 elems.
        // Region order r = 10j + w is memory order. 80 regions per tile.
        // ====================================================================
        const int tile  = blockIdx.x;
        const int baseQ = tile * (H_TILE / 4) - H_HALOQ;     // -512 at tile 0

        // ---- striped load + in-quad serial scan (zero carry-in) ----
        float v[32];                              // local partials, quad-major
        float exB[H_NPH];                         // lane-exclusive B per phase
        #pragma unroll
        for (int j = 0; j < H_NPH; j++) {
            const int gq = baseQ + j * BLOCKT + tid;
            float4 x = (gq >= 0) ? reinterpret_cast<const float4*>(y)[gq]
                                 : make_float4(0.f, 0.f, 0.f, 0.f);
            float p0 = alpha * x.x;
            float p1 = fmaf(a, p0, alpha * x.y);
            float p2 = fmaf(a, p1, alpha * x.z);
            float p3 = fmaf(a, p2, alpha * x.w);
            v[4*j+0] = p0; v[4*j+1] = p1; v[4*j+2] = p2; v[4*j+3] = p3;

            // warp inclusive scan of quad-aggregates (multiplier a^4 closed form)
            float B = p3;
            float m = a4;
            #pragma unroll
            for (int d = 1; d < 32; d <<= 1) {
                float pB = __shfl_up_sync(FULLMASK, B, d);
                if (lane >= d) B = fmaf(m, pB, B);
                m = m * m;
            }
            float e = __shfl_up_sync(FULLMASK, B, 1);
            exB[j] = (lane == 0) ? 0.f : e;
            if (lane == 31) sh_agg[10 * j + wid] = B;   // region aggregate
        }
        __syncthreads();

        // ---- warp 0: exclusive prefix over 80 regions (ratio a^128) ----
        if (wid == 0) {
            const float a128  = pow2k(a4, 5);            // a^128
            const float a4096 = pow2k(a128, 5);          // a^4096 (group ratio)
            const float Al = powi(a128, lane, 5);        // a^(128*lane)
            float carryB = 0.f;
            #pragma unroll
            for (int g = 0; g < 3; g++) {
                const int idx = 32 * g + lane;
                float Bv = (idx < 80) ? sh_agg[idx] : 0.f;
                float m = a128;
                #pragma unroll
                for (int d = 1; d < 32; d <<= 1) {
                    float pB = __shfl_up_sync(FULLMASK, Bv, d);
                    if (lane >= d) Bv = fmaf(m, pB, Bv);
                    m = m * m;
                }
                float ex = __shfl_up_sync(FULLMASK, Bv, 1);
                if (lane == 0) ex = 0.f;
                if (idx < 80) sh_P[idx] = fmaf(Al, carryB, ex);
                float tot = __shfl_sync(FULLMASK, Bv, 31);
                carryB = fmaf(a4096, carryB, tot);
            }
        }
        __syncthreads();

        // ---- apply carries + store striped directly from registers ----
        const float a4l = powi(a4, lane, 5);             // a^(4*lane)
        const float y0 = (tile == 0) ? __ldg(y) : 0.f;
        #pragma unroll
        for (int j = 1; j < H_NPH; j++) {                // j=0 is pure halo
            const int Q = j * BLOCKT + tid;
            if (Q < H_HALOQ) continue;                   // halo quads: no store
            const float cB = fmaf(a4l, sh_P[10 * j + wid], exB[j]);
            float e0 = fmaf(cB, a,  v[4*j+0]);
            float e1 = fmaf(cB, a2, v[4*j+1]);
            float e2 = fmaf(cB, a3, v[4*j+2]);
            float e3 = fmaf(cB, a4, v[4*j+3]);

            if (tile == 0) {                             // pin: s_t += a^(t+1)*y0
                float pw = a * powi(a4, Q - H_HALOQ, 11) * y0;
                e0 += pw; pw *= a;
                e1 += pw; pw *= a;
                e2 += pw; pw *= a;
                e3 += pw;
            }

            const long long gq = (long long)baseQ + Q;
            if (gq < (long long)LASTQ || tile != NT - 1) {
                __stcs(&reinterpret_cast<float4*>(out)[gq],
                       make_float4(e0, e1, e2, e3));
            } else {                                     // last quad: 3 elems
                float* op = out + 4 * gq;
                op[0] = e0; op[1] = e1; op[2] = e2;      // skip index T_LEN-1
            }
        }
        return;
    }

    // ========================================================================
    // FALLBACK PATH (tiny alpha): decoupled lookback, generation flags.
    // Work on tid < 256; warps 8-9 join barriers only. Buffer in dynamic SMEM.
    // ========================================================================
    float4* s4 = reinterpret_cast<float4*>(sdyn);        // padded: slot=Q+(Q>>3)

    if (tid == 0) sh_ticket = atomicAdd(&g_ctr, 1u);
    __syncthreads();
    const unsigned ticket = sh_ticket;
    const int tile = (int)(ticket & (NT - 1u));
    const unsigned fPart = 3u * (ticket >> NT_LOG2) + 1u;
    const unsigned fIncl = fPart + 1u;

    {
        const float4* yin = reinterpret_cast<const float4*>(y) + (size_t)tile * (F_TILE / 4);
        #pragma unroll
        for (int j = 0; j < 7; j++) {
            const int Q = j * BLOCKT + tid;
            if (Q < F_TILE / 4) s4[Q + (Q >> 3)] = yin[Q];
        }
    }
    __syncthreads();

    const float a8 = a4 * a4, a16 = a8 * a8;
    const float a32 = a16 * a16;

    float v[F_ITEMS];
    float B = 0.f, TexA = 1.f, TexB = 0.f, A1024 = 0.f;
    if (tid < F_WORK) {
        #pragma unroll
        for (int i = 0; i < 8; i++) {
            const int Q = 8 * tid + i;
            float4 q = s4[Q + (Q >> 3)];
            v[4*i+0] = q.x; v[4*i+1] = q.y; v[4*i+2] = q.z; v[4*i+3] = q.w;
        }
        {
            float p = 0.f;
            const bool first = (tile == 0 && tid == 0);
            #pragma unroll
            for (int i = 0; i < F_ITEMS; i++) {
                float aa = a, bb = alpha * v[i];
                if (first && i == 0) { aa = 0.f; bb = v[0]; }
                p = fmaf(aa, p, bb);
                v[i] = p;
            }
            B = p;
        }
        float m = a32;
        #pragma unroll
        for (int d = 1; d < 32; d <<= 1) {
            float pB = __shfl_up_sync(FULLMASK, B, d);
            if (lane >= d) B = fmaf(m, pB, B);
            m = m * m;
        }
        A1024 = m;
        if (lane == 31) sh_wB[wid] = B;
    }
    __syncthreads();

    if (tid < F_WORK) {
        float WB = 0.f;
        #pragma unroll
        for (int w = 0; w < F_NWARP; w++) if (w < wid) WB = fmaf(A1024, WB, sh_wB[w]);
        const float exA = powi(a32, lane, 5);
        float exB2 = __shfl_up_sync(FULLMASK, B, 1);
        if (lane == 0) exB2 = 0.f;
        TexB = fmaf(exA, WB, exB2);
        TexA = exA * powi(A1024, wid, 3);
    }

    float aggA = 0.f, aggB = 0.f;
    if (tid == 0) {
        float gB = 0.f;
        #pragma unroll
        for (int w = 0; w < F_NWARP; w++) gB = fmaf(A1024, gB, sh_wB[w]);
        float A8192 = A1024 * A1024; A8192 *= A8192; A8192 *= A8192;
        aggA = (tile == 0) ? 0.f : A8192;
        aggB = gB;
        if (tile == 0) {
            __stcg(&g_incl[0], make_float2(0.f, gB));
            st_release(&g_flag[0], fIncl);
            sh_carry = 0.f;
        } else {
            __stcg(&g_part[tile], make_float2(A8192, gB));
            st_release(&g_flag[tile], fPart);
        }
    }

    if (wid == 0 && tile > 0) {
        __syncwarp();
        float accA, accB;
        bool done;
        int pred = tile - 1;
        {   // fast path: wait only on the IMMEDIATE predecessor
            unsigned f = ld_acquire(&g_flag[pred]);
            while (f < fPart) { __nanosleep(32); f = ld_acquire(&g_flag[pred]); }
            float2 d2 = (f >= fIncl) ? __ldcg(&g_incl[pred]) : __ldcg(&g_part[pred]);
            accA = d2.x; accB = d2.y;
            done = (f >= fIncl) || (accA == 0.0f);
            pred--;
        }
        while (!done) {
            const int idx = pred - lane;
            unsigned st = 2u;
            if (idx >= 0) {
                unsigned f = ld_acquire(&g_flag[idx]);
                while (f < fPart) { __nanosleep(32); f = ld_acquire(&g_flag[idx]); }
                st = f - fPart + 1u;
            }
            float mA, mB;
            if (idx < 0) { mA = 1.f; mB = 0.f; }
            else {
                float2 d2 = (st == 2u) ? __ldcg(&g_incl[idx]) : __ldcg(&g_part[idx]);
                mA = d2.x; mB = d2.y;
            }
            const unsigned bal = __ballot_sync(FULLMASK, st == 2u);
            const int mm = bal ? (__ffs(bal) - 1) : 32;
            const int start = (mm < 32) ? mm : 31;

            float cA = 1.f, cB = 0.f;                // window earliest->latest
            for (int L = start; L >= 0; --L) {
                float sA = __shfl_sync(FULLMASK, mA, L);
                float sB = __shfl_sync(FULLMASK, mB, L);
                cB = fmaf(sA, cB, sB);
                cA = cA * sA;
            }
            float nB = fmaf(accA, cB, accB);         // acc = combine(window, acc)
            accA = cA * accA;
            accB = nB;
            done = (mm < 32) || (accA == 0.0f);
            pred -= 32;
        }
        if (lane == 0) {
            __stcg(&g_incl[tile], make_float2(accA * aggA, fmaf(aggA, accB, aggB)));
            st_release(&g_flag[tile], fIncl);
            sh_carry = accB;
        }
    }
    __syncthreads();

    if (tid < F_WORK) {
        const float c = fmaf(TexA, sh_carry, TexB);
        float cp = c * a;
        #pragma unroll
        for (int i = 0; i < F_ITEMS; i++) { v[i] += cp; cp *= a; }
        #pragma unroll
        for (int i = 0; i < 8; i++) {
            const int Q = 8 * tid + i;
            s4[Q + (Q >> 3)] = make_float4(v[4*i+0], v[4*i+1], v[4*i+2], v[4*i+3]);
        }
    }
    __syncthreads();

    {
        float4* o4 = reinterpret_cast<float4*>(out) + (size_t)tile * (F_TILE / 4);
        if (tile != NT - 1) {
            #pragma unroll
            for (int j = 0; j < 7; j++) {
                const int Q = j * BLOCKT + tid;
                if (Q < F_TILE / 4) __stcs(&o4[Q], s4[Q + (Q >> 3)]);
            }
        } else {
            const long long tbase = (long long)tile * F_TILE;
            #pragma unroll
            for (int j = 0; j < 7; j++) {
                const int Q = j * BLOCKT + tid;
                if (Q >= F_TILE / 4) continue;
                float4 q = s4[Q + (Q >> 3)];
                const long long g = tbase + 4LL * Q;
                if (g + 4 <= (long long)(T_LEN - 1)) {
                    __stcs(&o4[Q], q);
                } else {
                    float* op = out + g;
                    if (g + 0 < (long long)(T_LEN - 1)) op[0] = q.x;
                    if (g + 1 < (long long)(T_LEN - 1)) op[1] = q.y;
                    if (g + 2 < (long long)(T_LEN - 1)) op[2] = q.z;
                    if (g + 3 < (long long)(T_LEN - 1)) op[3] = q.w;
                }
            }
        }
    }
}

extern "C" void kernel_launch(void* const* d_in, const int* in_sizes, int n_in,
                              void* d_out, int out_size) {
    const float* y     = (const float*)d_in[0];   // timeseries, T_LEN fp32
    const float* alpha = (const float*)d_in[1];   // 1 fp32
    float* out = (float*)d_out;                   // T_LEN-1 fp32
    (void)in_sizes; (void)n_in; (void)out_size;

    ses_fused<<<NT, BLOCKT, F_SMEM>>>(y, alpha, out);
}